// round 2
// baseline (speedup 1.0000x reference)
#include <cuda_runtime.h>
#include <math.h>

#define NUM_B 8
#define NUM_A 131072
#define NUM_C 4
#define NUM_M 64
#define BLOCK 256

// Per-sample accumulators: [cls_sum, xy_sum, ang_sum, num_pos]
__device__ double g_acc[NUM_B][4];

__global__ void zero_acc_kernel() {
    int i = threadIdx.x;
    if (i < NUM_B * 4) ((double*)g_acc)[i] = 0.0;
}

__global__ __launch_bounds__(BLOCK) void focal_main_kernel(
    const float* __restrict__ cls,   // (B, A, C)
    const float* __restrict__ reg,   // (B, A, 3)
    const float* __restrict__ anc,   // (A, 3)
    const float* __restrict__ ann)   // (B, M, 4)
{
    // Annotations for this sample: xy interleaved (for float4 loads), alpha, label
    __shared__ float s_xy[NUM_M * 2];   // x0,y0,x1,y1,...
    __shared__ float s_al[NUM_M];
    __shared__ float s_lb[NUM_M];

    const int b   = blockIdx.y;
    const int tid = threadIdx.x;

    if (tid < NUM_M) {
        const float* a4 = ann + ((size_t)b * NUM_M + tid) * 4;
        float x = a4[0], y = a4[1], al = a4[2], lb = a4[3];
        bool valid = (lb != -1.0f);
        // invalid -> huge coords: d2 ~ 1e36, never argmin (48 valid always exist),
        // never below any threshold.
        s_xy[2 * tid + 0] = valid ? x : 1e18f;
        s_xy[2 * tid + 1] = valid ? y : 1e18f;
        s_al[tid] = al;
        s_lb[tid] = lb;
    }
    __syncthreads();

    const int a = blockIdx.x * BLOCK + tid;

    const float ax  = anc[3 * a + 0];
    const float ay  = anc[3 * a + 1];
    const float aal = anc[3 * a + 2];

    // Prefetch per-anchor data now; latency hidden behind the 64-iter loop.
    const float4 c4 = *(const float4*)(cls + ((size_t)b * NUM_A + a) * NUM_C);
    const float* r3 = reg + ((size_t)b * NUM_A + a) * 3;
    const float rx = r3[0], ry = r3[1], ra = r3[2];

    // 64-way squared-distance argmin (strict < keeps first-index tie semantics).
    float best = 3.4e38f;
    int bestm = 0;
    const float4* pxy = (const float4*)s_xy;
    #pragma unroll
    for (int j = 0; j < NUM_M / 2; j++) {
        float4 q = pxy[j];
        {
            float dx = ax - q.x;
            float dy = ay - q.y;
            float d2 = fmaf(dy, dy, dx * dx);
            bool lt = d2 < best;
            best  = lt ? d2 : best;
            bestm = lt ? 2 * j : bestm;
        }
        {
            float dx = ax - q.z;
            float dy = ay - q.w;
            float d2 = fmaf(dy, dy, dx * dx);
            bool lt = d2 < best;
            best  = lt ? d2 : best;
            bestm = lt ? 2 * j + 1 : bestm;
        }
    }

    const float bx  = s_xy[2 * bestm + 0];
    const float by  = s_xy[2 * bestm + 1];
    const float bal = s_al[bestm];

    const float dang = fabsf(aal - bal);

    // sqrt-free thresholds: dxy<20 <=> d2<400 ; dxy>=30 <=> d2>=900
    const bool positive   = (best < 400.0f) && (dang < 15.0f);
    const bool background = (best >= 900.0f) || (dang >= 22.5f);
    const bool care       = positive || background;   // mutually exclusive sets

    float cls_acc = 0.0f;
    if (care) {
        int label = positive ? min(max((int)s_lb[bestm], 0), NUM_C - 1) : -1;
        float cv[4] = {c4.x, c4.y, c4.z, c4.w};
        #pragma unroll
        for (int c = 0; c < NUM_C; c++) {
            float p = fminf(fmaxf(cv[c], 1e-4f), 1.0f - 1e-4f);
            bool is1 = (c == label);
            // t==1: w = 0.95*(1-p)^2, bce = -log(p)
            // t==0: w = 0.05*p^2,     bce = -log(1-p)
            float q = is1 ? (1.0f - p) : p;
            float w = (is1 ? 0.95f : 0.05f) * q * q;
            float bce = -__logf(1.0f - q);   // log(p) if is1 else log(1-p)
            cls_acc = fmaf(w, bce, cls_acc);
        }
    }

    float xy_acc = 0.0f, ang_acc = 0.0f;
    const float posf = positive ? 1.0f : 0.0f;
    if (positive) {
        // regression targets: assigned annot - anchor
        float tx = bx  - ax;
        float ty = by  - ay;
        float ta = bal - aal;
        float dxr = fabsf(tx - rx);
        float dyr = fabsf(ty - ry);
        const float inv9 = 1.0f / 9.0f;
        float lx = (dxr <= inv9) ? (4.5f * dxr * dxr) : (dxr - 0.5f * inv9);
        float ly = (dyr <= inv9) ? (4.5f * dyr * dyr) : (dyr - 0.5f * inv9);
        xy_acc = lx + ly;
        ang_acc = fmaxf((fabsf(ta - ra) - 10.0f) * 0.2f, 0.0f);
    }

    // ---- block reduction: 4 quantities ----
    float v0 = cls_acc, v1 = xy_acc, v2 = ang_acc, v3 = posf;
    #pragma unroll
    for (int o = 16; o > 0; o >>= 1) {
        v0 += __shfl_down_sync(0xffffffffu, v0, o);
        v1 += __shfl_down_sync(0xffffffffu, v1, o);
        v2 += __shfl_down_sync(0xffffffffu, v2, o);
        v3 += __shfl_down_sync(0xffffffffu, v3, o);
    }
    __shared__ float red[BLOCK / 32][4];
    const int wid = tid >> 5, lid = tid & 31;
    if (lid == 0) {
        red[wid][0] = v0; red[wid][1] = v1; red[wid][2] = v2; red[wid][3] = v3;
    }
    __syncthreads();
    if (tid < 4) {
        float s = 0.0f;
        #pragma unroll
        for (int w = 0; w < BLOCK / 32; w++) s += red[w][tid];
        atomicAdd(&g_acc[b][tid], (double)s);
    }
}

__global__ void finalize_kernel(float* __restrict__ out) {
    if (threadIdx.x == 0) {
        double cs = 0.0, xs = 0.0, as = 0.0;
        #pragma unroll
        for (int b = 0; b < NUM_B; b++) {
            double denom = fmax(g_acc[b][3], 1.0);
            cs += g_acc[b][0] / denom;
            xs += g_acc[b][1] / (2.0 * denom);
            as += g_acc[b][2] / denom;
        }
        out[0] = (float)(cs / NUM_B);
        out[1] = (float)(xs / NUM_B);
        out[2] = (float)(as / NUM_B);
    }
}

extern "C" void kernel_launch(void* const* d_in, const int* in_sizes, int n_in,
                              void* d_out, int out_size) {
    (void)in_sizes; (void)n_in; (void)out_size;
    const float* cls = (const float*)d_in[0];   // (B, A, C)
    const float* reg = (const float*)d_in[1];   // (B, A, 3)
    const float* anc = (const float*)d_in[2];   // (1, A, 3)
    const float* ann = (const float*)d_in[3];   // (B, M, 4)
    float* out = (float*)d_out;

    zero_acc_kernel<<<1, 32>>>();
    dim3 grid(NUM_A / BLOCK, NUM_B);
    focal_main_kernel<<<grid, BLOCK>>>(cls, reg, anc, ann);
    finalize_kernel<<<1, 32>>>(out);
}

// round 3
// speedup vs baseline: 1.4062x; 1.4062x over previous
#include <cuda_runtime.h>
#include <math.h>

#define NUM_B 8
#define NUM_A 131072
#define NUM_C 4
#define NUM_M 64
#define BLOCK 256
#define GRIDX (NUM_A / BLOCK)      // 512
#define NBLOCKS (GRIDX * NUM_B)    // 4096

// Per-block partials: [cls_sum, xy_sum, ang_sum, num_pos]. Written with plain
// stores every run (no zeroing needed).
__device__ float4 g_part[NBLOCKS];
__device__ unsigned int g_count = 0;   // self-resetting completion counter

#define ADD_F32X2(out, a, b) \
    asm("add.rn.f32x2 %0, %1, %2;" : "=l"(out) : "l"(a), "l"(b))
#define MUL_F32X2(out, a, b) \
    asm("mul.rn.f32x2 %0, %1, %2;" : "=l"(out) : "l"(a), "l"(b))
#define PACK_F32X2(out, lo, hi) \
    asm("mov.b64 %0, {%1, %2};" : "=l"(out) : "r"(lo), "r"(hi))
#define UNPACK_F32X2(lo, hi, in) \
    asm("mov.b64 {%0, %1}, %2;" : "=r"(lo), "=r"(hi) : "l"(in))

__global__ __launch_bounds__(BLOCK) void focal_fused_kernel(
    const float* __restrict__ cls,   // (B, A, C)
    const float* __restrict__ reg,   // (B, A, 3)
    const float* __restrict__ anc,   // (A, 3)
    const float* __restrict__ ann,   // (B, M, 4)
    float* __restrict__ out)         // (3,)
{
    // Annotation coords stored NEGATED + xy-interleaved so the distance
    // subtract becomes a packed f32x2 add.
    __shared__ __align__(16) float s_xy[NUM_M * 2];   // -x0,-y0,-x1,-y1,...
    __shared__ float s_al[NUM_M];
    __shared__ float s_lb[NUM_M];

    const int b   = blockIdx.y;
    const int tid = threadIdx.x;

    if (tid < NUM_M) {
        const float* a4 = ann + ((size_t)b * NUM_M + tid) * 4;
        float x = a4[0], y = a4[1], al = a4[2], lb = a4[3];
        bool valid = (lb != -1.0f);
        // invalid -> coords pushed to -1e18: d2 ~ 1e36, never wins argmin,
        // never passes any threshold.
        s_xy[2 * tid + 0] = valid ? -x : -1e18f;
        s_xy[2 * tid + 1] = valid ? -y : -1e18f;
        s_al[tid] = al;
        s_lb[tid] = lb;
    }
    __syncthreads();

    const int a = blockIdx.x * BLOCK + tid;

    const float ax  = anc[3 * a + 0];
    const float ay  = anc[3 * a + 1];
    const float aal = anc[3 * a + 2];

    // Prefetch per-anchor data; latency hidden behind the 64-iter loop.
    const float4 c4 = *(const float4*)(cls + ((size_t)b * NUM_A + a) * NUM_C);
    const float* r3 = reg + ((size_t)b * NUM_A + a) * 3;
    const float rx = r3[0], ry = r3[1], ra = r3[2];

    unsigned long long axy;
    PACK_F32X2(axy, __float_as_uint(ax), __float_as_uint(ay));

    // 64-way argmin via bit-packed keys: positive-float bits are u32-ordered;
    // low 6 bits replaced by annotation index. Ties (within 64 ulps) resolve
    // to the lower index == first-index argmin semantics.
    unsigned int bestkey = 0xffffffffu;
    const unsigned int KMASK = 0xffffffc0u;
    const ulonglong2* pq = (const ulonglong2*)s_xy;
    #pragma unroll
    for (int j = 0; j < NUM_M / 2; j++) {
        ulonglong2 q = pq[j];
        {
            unsigned long long d, s;
            ADD_F32X2(d, axy, q.x);          // (ax-x, ay-y)
            MUL_F32X2(s, d, d);              // (dx^2, dy^2)
            unsigned lo, hi;
            UNPACK_F32X2(lo, hi, s);
            float d2 = __uint_as_float(lo) + __uint_as_float(hi);
            unsigned key = (__float_as_uint(d2) & KMASK) | (unsigned)(2 * j);
            bestkey = min(bestkey, key);
        }
        {
            unsigned long long d, s;
            ADD_F32X2(d, axy, q.y);
            MUL_F32X2(s, d, d);
            unsigned lo, hi;
            UNPACK_F32X2(lo, hi, s);
            float d2 = __uint_as_float(lo) + __uint_as_float(hi);
            unsigned key = (__float_as_uint(d2) & KMASK) | (unsigned)(2 * j + 1);
            bestkey = min(bestkey, key);
        }
    }
    const int bestm = (int)(bestkey & 63u);

    // Recover exact values for the winner (thresholds stay exact).
    const float bx  = -s_xy[2 * bestm + 0];
    const float by  = -s_xy[2 * bestm + 1];
    const float bal = s_al[bestm];
    const float ddx = ax - bx;
    const float ddy = ay - by;
    const float best = fmaf(ddy, ddy, ddx * ddx);
    const float dang = fabsf(aal - bal);

    // sqrt-free thresholds: dxy<20 <=> d2<400 ; dxy>=30 <=> d2>=900
    const bool positive   = (best < 400.0f) && (dang < 15.0f);
    const bool background = (best >= 900.0f) || (dang >= 22.5f);
    const bool care       = positive || background;

    float cls_acc = 0.0f;
    if (care) {
        int label = positive ? min(max((int)s_lb[bestm], 0), NUM_C - 1) : -1;
        float cv[4] = {c4.x, c4.y, c4.z, c4.w};
        #pragma unroll
        for (int c = 0; c < NUM_C; c++) {
            float p = fminf(fmaxf(cv[c], 1e-4f), 1.0f - 1e-4f);
            bool is1 = (c == label);
            // t==1: w = 0.95*(1-p)^2, bce = -log(p)
            // t==0: w = 0.05*p^2,     bce = -log(1-p)
            float q = is1 ? (1.0f - p) : p;
            float w = (is1 ? 0.95f : 0.05f) * q * q;
            float bce = -__logf(1.0f - q);
            cls_acc = fmaf(w, bce, cls_acc);
        }
    }

    float xy_acc = 0.0f, ang_acc = 0.0f;
    const float posf = positive ? 1.0f : 0.0f;
    if (positive) {
        float tx = bx  - ax;
        float ty = by  - ay;
        float ta = bal - aal;
        float dxr = fabsf(tx - rx);
        float dyr = fabsf(ty - ry);
        const float inv9 = 1.0f / 9.0f;
        float lx = (dxr <= inv9) ? (4.5f * dxr * dxr) : (dxr - 0.5f * inv9);
        float ly = (dyr <= inv9) ? (4.5f * dyr * dyr) : (dyr - 0.5f * inv9);
        xy_acc = lx + ly;
        ang_acc = fmaxf((fabsf(ta - ra) - 10.0f) * 0.2f, 0.0f);
    }

    // ---- block reduction: 4 quantities ----
    float v0 = cls_acc, v1 = xy_acc, v2 = ang_acc, v3 = posf;
    #pragma unroll
    for (int o = 16; o > 0; o >>= 1) {
        v0 += __shfl_down_sync(0xffffffffu, v0, o);
        v1 += __shfl_down_sync(0xffffffffu, v1, o);
        v2 += __shfl_down_sync(0xffffffffu, v2, o);
        v3 += __shfl_down_sync(0xffffffffu, v3, o);
    }
    __shared__ float red[BLOCK / 32][4];
    const int wid = tid >> 5, lid = tid & 31;
    if (lid == 0) {
        red[wid][0] = v0; red[wid][1] = v1; red[wid][2] = v2; red[wid][3] = v3;
    }
    __syncthreads();
    if (tid < 4) {
        float s = 0.0f;
        #pragma unroll
        for (int w = 0; w < BLOCK / 32; w++) s += red[w][tid];
        ((float*)&g_part[(size_t)b * GRIDX + blockIdx.x])[tid] = s;
        __threadfence();   // publish partials before the ticket increment
    }
    __syncthreads();

    // ---- last-block finalize (fused, no extra launches) ----
    __shared__ bool is_last;
    if (tid == 0) {
        unsigned v = atomicAdd(&g_count, 1u);
        is_last = (v == NBLOCKS - 1);
    }
    __syncthreads();
    if (!is_last) return;
    if (tid == 0) g_count = 0;   // reset for next graph replay

    // 8 warps, warp w reduces sample b=w over its 512 partials.
    __shared__ float s_res[NUM_B][3];
    const int w = tid >> 5, l = tid & 31;
    float4 acc = make_float4(0.f, 0.f, 0.f, 0.f);
    #pragma unroll
    for (int k = 0; k < GRIDX / 32; k++) {
        float4 p = g_part[(size_t)w * GRIDX + l + 32 * k];
        acc.x += p.x; acc.y += p.y; acc.z += p.z; acc.w += p.w;
    }
    #pragma unroll
    for (int o = 16; o > 0; o >>= 1) {
        acc.x += __shfl_down_sync(0xffffffffu, acc.x, o);
        acc.y += __shfl_down_sync(0xffffffffu, acc.y, o);
        acc.z += __shfl_down_sync(0xffffffffu, acc.z, o);
        acc.w += __shfl_down_sync(0xffffffffu, acc.w, o);
    }
    if (l == 0) {
        float denom = fmaxf(acc.w, 1.0f);
        s_res[w][0] = acc.x / denom;
        s_res[w][1] = acc.y / (2.0f * denom);
        s_res[w][2] = acc.z / denom;
    }
    __syncthreads();
    if (tid == 0) {
        float c = 0.f, x = 0.f, an = 0.f;
        #pragma unroll
        for (int bb = 0; bb < NUM_B; bb++) {
            c += s_res[bb][0]; x += s_res[bb][1]; an += s_res[bb][2];
        }
        out[0] = c  * (1.0f / NUM_B);
        out[1] = x  * (1.0f / NUM_B);
        out[2] = an * (1.0f / NUM_B);
    }
}

extern "C" void kernel_launch(void* const* d_in, const int* in_sizes, int n_in,
                              void* d_out, int out_size) {
    (void)in_sizes; (void)n_in; (void)out_size;
    const float* cls = (const float*)d_in[0];   // (B, A, C)
    const float* reg = (const float*)d_in[1];   // (B, A, 3)
    const float* anc = (const float*)d_in[2];   // (1, A, 3)
    const float* ann = (const float*)d_in[3];   // (B, M, 4)
    float* out = (float*)d_out;

    dim3 grid(GRIDX, NUM_B);
    focal_fused_kernel<<<grid, BLOCK>>>(cls, reg, anc, ann, out);
}

// round 4
// speedup vs baseline: 1.4410x; 1.0248x over previous
#include <cuda_runtime.h>
#include <math.h>

#define NUM_B 8
#define NUM_A 131072
#define NUM_C 4
#define NUM_M 64
#define BLOCK 256
#define GRIDX (NUM_A / BLOCK)      // 512
#define NBLOCKS (GRIDX * NUM_B)    // 4096

// Per-block partials: [cls_sum, xy_sum, ang_sum, num_pos]. Plain stores each run.
__device__ float4 g_part[NBLOCKS];
__device__ unsigned int g_count = 0;   // self-resetting completion counter

#define ADD_F32X2(out, a, b) \
    asm("add.rn.f32x2 %0, %1, %2;" : "=l"(out) : "l"(a), "l"(b))
#define MUL_F32X2(out, a, b) \
    asm("mul.rn.f32x2 %0, %1, %2;" : "=l"(out) : "l"(a), "l"(b))
#define FMA_F32X2(out, a, b, c) \
    asm("fma.rn.f32x2 %0, %1, %2, %3;" : "=l"(out) : "l"(a), "l"(b), "l"(c))
#define PACK_F32X2(out, lo, hi) \
    asm("mov.b64 %0, {%1, %2};" : "=l"(out) : "r"(lo), "r"(hi))

__global__ __launch_bounds__(BLOCK) void focal_fused_kernel(
    const float* __restrict__ cls,   // (B, A, C)
    const float* __restrict__ reg,   // (B, A, 3)
    const float* __restrict__ anc,   // (A, 3)
    const float* __restrict__ ann,   // (B, M, 4)
    float* __restrict__ out)         // (3,)
{
    // Pair-of-structs, NEGATED coords: float4 j = (-x_{2j}, -x_{2j+1}, -y_{2j}, -y_{2j+1})
    // so packed f32x2 ADD does the subtract for two annotations at once.
    __shared__ __align__(16) float s_pair[NUM_M * 2];
    __shared__ float s_al[NUM_M];
    __shared__ float s_lb[NUM_M];

    const int b   = blockIdx.y;
    const int tid = threadIdx.x;

    if (tid < NUM_M) {
        const float* a4 = ann + ((size_t)b * NUM_M + tid) * 4;
        float x = a4[0], y = a4[1], al = a4[2], lb = a4[3];
        bool valid = (lb != -1.0f);
        // invalid -> coords pushed to -1e18: d2 ~ 1e36, never wins argmin,
        // never passes any threshold.
        const int j = tid >> 1, slot = tid & 1;
        s_pair[4 * j + slot]     = valid ? -x : -1e18f;
        s_pair[4 * j + 2 + slot] = valid ? -y : -1e18f;
        s_al[tid] = al;
        s_lb[tid] = lb;
    }
    __syncthreads();

    const int a = blockIdx.x * BLOCK + tid;

    const float ax  = anc[3 * a + 0];
    const float ay  = anc[3 * a + 1];
    const float aal = anc[3 * a + 2];

    // Prefetch per-anchor data; latency hidden behind the 64-iter loop.
    const float4 c4 = *(const float4*)(cls + ((size_t)b * NUM_A + a) * NUM_C);
    const float* r3 = reg + ((size_t)b * NUM_A + a) * 3;
    const float rx = r3[0], ry = r3[1], ra = r3[2];

    unsigned long long axx, ayy;
    {
        unsigned axb = __float_as_uint(ax), ayb = __float_as_uint(ay);
        PACK_F32X2(axx, axb, axb);   // (ax, ax)
        PACK_F32X2(ayy, ayb, ayb);   // (ay, ay)
    }

    // 64-way argmin via bit-packed keys: positive-float bits are u32-ordered;
    // low 6 bits replaced by annotation index. Ties (within 64 ulps) resolve
    // to the lower index == first-index argmin semantics.
    unsigned int bestkey = 0xffffffffu;
    const unsigned int KMASK = 0xffffffc0u;
    const ulonglong2* pq = (const ulonglong2*)s_pair;
    #pragma unroll
    for (int j = 0; j < NUM_M / 2; j++) {
        ulonglong2 q = pq[j];                 // .x = (-x0,-x1), .y = (-y0,-y1)
        unsigned long long dxp, dyp, tp, d2p;
        ADD_F32X2(dxp, axx, q.x);             // (ax-x0, ax-x1)
        ADD_F32X2(dyp, ayy, q.y);             // (ay-y0, ay-y1)
        MUL_F32X2(tp, dxp, dxp);              // (dx0^2, dx1^2)
        FMA_F32X2(d2p, dyp, dyp, tp);         // (d2_0, d2_1)  == fmaf(dy,dy,dx*dx)
        unsigned lo = (unsigned)d2p;          // register-half access, no MOV
        unsigned hi = (unsigned)(d2p >> 32);
        unsigned key0 = (lo & KMASK) | (unsigned)(2 * j);
        unsigned key1 = (hi & KMASK) | (unsigned)(2 * j + 1);
        bestkey = min(bestkey, min(key0, key1));
    }
    const int bestm = (int)(bestkey & 63u);

    // Recover exact values for the winner (thresholds stay exact).
    const int bj = bestm >> 1, bslot = bestm & 1;
    const float bx  = -s_pair[4 * bj + bslot];
    const float by  = -s_pair[4 * bj + 2 + bslot];
    const float bal = s_al[bestm];
    const float ddx = ax - bx;
    const float ddy = ay - by;
    const float best = fmaf(ddy, ddy, ddx * ddx);
    const float dang = fabsf(aal - bal);

    // sqrt-free thresholds: dxy<20 <=> d2<400 ; dxy>=30 <=> d2>=900
    const bool positive   = (best < 400.0f) && (dang < 15.0f);
    const bool background = (best >= 900.0f) || (dang >= 22.5f);
    const bool care       = positive || background;

    float cls_acc = 0.0f;
    if (care) {
        int label = positive ? min(max((int)s_lb[bestm], 0), NUM_C - 1) : -1;
        float cv[4] = {c4.x, c4.y, c4.z, c4.w};
        #pragma unroll
        for (int c = 0; c < NUM_C; c++) {
            float p = fminf(fmaxf(cv[c], 1e-4f), 1.0f - 1e-4f);
            bool is1 = (c == label);
            // t==1: w = 0.95*(1-p)^2, bce = -log(p)
            // t==0: w = 0.05*p^2,     bce = -log(1-p)
            float q = is1 ? (1.0f - p) : p;
            float w = (is1 ? 0.95f : 0.05f) * q * q;
            float bce = -__logf(1.0f - q);
            cls_acc = fmaf(w, bce, cls_acc);
        }
    }

    float xy_acc = 0.0f, ang_acc = 0.0f;
    const float posf = positive ? 1.0f : 0.0f;
    if (positive) {
        float tx = bx  - ax;
        float ty = by  - ay;
        float ta = bal - aal;
        float dxr = fabsf(tx - rx);
        float dyr = fabsf(ty - ry);
        const float inv9 = 1.0f / 9.0f;
        float lx = (dxr <= inv9) ? (4.5f * dxr * dxr) : (dxr - 0.5f * inv9);
        float ly = (dyr <= inv9) ? (4.5f * dyr * dyr) : (dyr - 0.5f * inv9);
        xy_acc = lx + ly;
        ang_acc = fmaxf((fabsf(ta - ra) - 10.0f) * 0.2f, 0.0f);
    }

    // ---- block reduction: 4 quantities ----
    float v0 = cls_acc, v1 = xy_acc, v2 = ang_acc, v3 = posf;
    #pragma unroll
    for (int o = 16; o > 0; o >>= 1) {
        v0 += __shfl_down_sync(0xffffffffu, v0, o);
        v1 += __shfl_down_sync(0xffffffffu, v1, o);
        v2 += __shfl_down_sync(0xffffffffu, v2, o);
        v3 += __shfl_down_sync(0xffffffffu, v3, o);
    }
    __shared__ float red[BLOCK / 32][4];
    const int wid = tid >> 5, lid = tid & 31;
    if (lid == 0) {
        red[wid][0] = v0; red[wid][1] = v1; red[wid][2] = v2; red[wid][3] = v3;
    }
    __syncthreads();
    if (tid < 4) {
        float s = 0.0f;
        #pragma unroll
        for (int w = 0; w < BLOCK / 32; w++) s += red[w][tid];
        ((float*)&g_part[(size_t)b * GRIDX + blockIdx.x])[tid] = s;
        __threadfence();   // publish partials before the ticket increment
    }
    __syncthreads();

    // ---- last-block finalize (fused, no extra launches) ----
    __shared__ bool is_last;
    if (tid == 0) {
        unsigned v = atomicAdd(&g_count, 1u);
        is_last = (v == NBLOCKS - 1);
    }
    __syncthreads();
    if (!is_last) return;
    if (tid == 0) g_count = 0;   // reset for next graph replay

    // 8 warps, warp w reduces sample b=w over its 512 partials.
    __shared__ float s_res[NUM_B][3];
    const int w = tid >> 5, l = tid & 31;
    float4 acc = make_float4(0.f, 0.f, 0.f, 0.f);
    #pragma unroll
    for (int k = 0; k < GRIDX / 32; k++) {
        float4 p = g_part[(size_t)w * GRIDX + l + 32 * k];
        acc.x += p.x; acc.y += p.y; acc.z += p.z; acc.w += p.w;
    }
    #pragma unroll
    for (int o = 16; o > 0; o >>= 1) {
        acc.x += __shfl_down_sync(0xffffffffu, acc.x, o);
        acc.y += __shfl_down_sync(0xffffffffu, acc.y, o);
        acc.z += __shfl_down_sync(0xffffffffu, acc.z, o);
        acc.w += __shfl_down_sync(0xffffffffu, acc.w, o);
    }
    if (l == 0) {
        float denom = fmaxf(acc.w, 1.0f);
        s_res[w][0] = acc.x / denom;
        s_res[w][1] = acc.y / (2.0f * denom);
        s_res[w][2] = acc.z / denom;
    }
    __syncthreads();
    if (tid == 0) {
        float c = 0.f, x = 0.f, an = 0.f;
        #pragma unroll
        for (int bb = 0; bb < NUM_B; bb++) {
            c += s_res[bb][0]; x += s_res[bb][1]; an += s_res[bb][2];
        }
        out[0] = c  * (1.0f / NUM_B);
        out[1] = x  * (1.0f / NUM_B);
        out[2] = an * (1.0f / NUM_B);
    }
}

extern "C" void kernel_launch(void* const* d_in, const int* in_sizes, int n_in,
                              void* d_out, int out_size) {
    (void)in_sizes; (void)n_in; (void)out_size;
    const float* cls = (const float*)d_in[0];   // (B, A, C)
    const float* reg = (const float*)d_in[1];   // (B, A, 3)
    const float* anc = (const float*)d_in[2];   // (1, A, 3)
    const float* ann = (const float*)d_in[3];   // (B, M, 4)
    float* out = (float*)d_out;

    dim3 grid(GRIDX, NUM_B);
    focal_fused_kernel<<<grid, BLOCK>>>(cls, reg, anc, ann, out);
}

// round 5
// speedup vs baseline: 1.6996x; 1.1794x over previous
#include <cuda_runtime.h>
#include <math.h>

#define NUM_B 8
#define NUM_A 131072
#define NUM_C 4
#define NUM_M 64
#define BLOCK 256
#define APT 4                              // anchors per thread
#define GRIDX (NUM_A / (BLOCK * APT))      // 128
#define NBLOCKS (GRIDX * NUM_B)            // 1024

// Per-block partials: [cls_sum, xy_sum, ang_sum, num_pos]. Plain stores each run.
__device__ float4 g_part[NBLOCKS];
__device__ unsigned int g_count = 0;   // self-resetting completion counter

#define ADD_F32X2(out, a, b) \
    asm("add.rn.f32x2 %0, %1, %2;" : "=l"(out) : "l"(a), "l"(b))
#define MUL_F32X2(out, a, b) \
    asm("mul.rn.f32x2 %0, %1, %2;" : "=l"(out) : "l"(a), "l"(b))
#define FMA_F32X2(out, a, b, c) \
    asm("fma.rn.f32x2 %0, %1, %2, %3;" : "=l"(out) : "l"(a), "l"(b), "l"(c))
#define PACK_F32X2(out, lo, hi) \
    asm("mov.b64 %0, {%1, %2};" : "=l"(out) : "r"(lo), "r"(hi))

__global__ __launch_bounds__(BLOCK) void focal_fused_kernel(
    const float* __restrict__ cls,   // (B, A, C)
    const float* __restrict__ reg,   // (B, A, 3)
    const float* __restrict__ anc,   // (A, 3)
    const float* __restrict__ ann,   // (B, M, 4)
    float* __restrict__ out)         // (3,)
{
    // Pair-of-structs, NEGATED coords: float4 j = (-x_{2j}, -x_{2j+1}, -y_{2j}, -y_{2j+1})
    __shared__ __align__(16) float s_pair[NUM_M * 2];
    __shared__ float s_al[NUM_M];
    __shared__ float s_lb[NUM_M];

    const int b   = blockIdx.y;
    const int tid = threadIdx.x;

    if (tid < NUM_M) {
        const float* a4 = ann + ((size_t)b * NUM_M + tid) * 4;
        float x = a4[0], y = a4[1], al = a4[2], lb = a4[3];
        bool valid = (lb != -1.0f);
        // invalid -> coords pushed to -1e18: d2 ~ 1e36, never wins argmin,
        // never passes any threshold.
        const int j = tid >> 1, slot = tid & 1;
        s_pair[4 * j + slot]     = valid ? -x : -1e18f;
        s_pair[4 * j + 2 + slot] = valid ? -y : -1e18f;
        s_al[tid] = al;
        s_lb[tid] = lb;
    }
    __syncthreads();

    // 4 anchors per thread, stride-BLOCK for coalescing.
    const int a0 = blockIdx.x * (BLOCK * APT) + tid;

    float ax[APT], ay[APT], aal[APT];
    unsigned long long axx[APT], ayy[APT];
    float4 c4[APT];
    float rx[APT], ry[APT], ra[APT];

    #pragma unroll
    for (int k = 0; k < APT; k++) {
        const int a = a0 + k * BLOCK;
        ax[k]  = anc[3 * a + 0];
        ay[k]  = anc[3 * a + 1];
        aal[k] = anc[3 * a + 2];
        c4[k] = *(const float4*)(cls + ((size_t)b * NUM_A + a) * NUM_C);
        const float* r3 = reg + ((size_t)b * NUM_A + a) * 3;
        rx[k] = r3[0]; ry[k] = r3[1]; ra[k] = r3[2];
        unsigned axb = __float_as_uint(ax[k]), ayb = __float_as_uint(ay[k]);
        PACK_F32X2(axx[k], axb, axb);
        PACK_F32X2(ayy[k], ayb, ayb);
    }

    // 64-way argmin per anchor via bit-packed keys (positive-float bits are
    // u32-ordered; low 6 bits replaced by annotation index, ties -> lower index).
    unsigned int bestkey[APT];
    #pragma unroll
    for (int k = 0; k < APT; k++) bestkey[k] = 0xffffffffu;
    const unsigned int KMASK = 0xffffffc0u;
    const ulonglong2* pq = (const ulonglong2*)s_pair;

    #pragma unroll
    for (int j = 0; j < NUM_M / 2; j++) {
        ulonglong2 q = pq[j];                 // one LDS.128 feeds all 4 anchors
        const unsigned i0 = (unsigned)(2 * j), i1 = (unsigned)(2 * j + 1);
        #pragma unroll
        for (int k = 0; k < APT; k++) {
            unsigned long long dxp, dyp, tp, d2p;
            ADD_F32X2(dxp, axx[k], q.x);      // (ax-x0, ax-x1)
            ADD_F32X2(dyp, ayy[k], q.y);      // (ay-y0, ay-y1)
            MUL_F32X2(tp, dxp, dxp);
            FMA_F32X2(d2p, dyp, dyp, tp);     // == fmaf(dy,dy,dx*dx) per lane
            unsigned lo = (unsigned)d2p;
            unsigned hi = (unsigned)(d2p >> 32);
            unsigned key0 = (lo & KMASK) | i0;
            unsigned key1 = (hi & KMASK) | i1;
            bestkey[k] = min(bestkey[k], min(key0, key1));
        }
    }

    // ---- per-anchor epilogue, accumulated locally over the 4 anchors ----
    float v0 = 0.0f, v1 = 0.0f, v2 = 0.0f, v3 = 0.0f;
    #pragma unroll
    for (int k = 0; k < APT; k++) {
        const int bestm = (int)(bestkey[k] & 63u);
        const int bj = bestm >> 1, bslot = bestm & 1;
        const float bx  = -s_pair[4 * bj + bslot];
        const float by  = -s_pair[4 * bj + 2 + bslot];
        const float bal = s_al[bestm];
        const float ddx = ax[k] - bx;
        const float ddy = ay[k] - by;
        const float best = fmaf(ddy, ddy, ddx * ddx);   // exact winner d2
        const float dang = fabsf(aal[k] - bal);

        // sqrt-free thresholds: dxy<20 <=> d2<400 ; dxy>=30 <=> d2>=900
        const bool positive   = (best < 400.0f) && (dang < 15.0f);
        const bool background = (best >= 900.0f) || (dang >= 22.5f);
        const bool care       = positive || background;

        if (care) {
            int label = positive ? min(max((int)s_lb[bestm], 0), NUM_C - 1) : -1;
            float cv[4] = {c4[k].x, c4[k].y, c4[k].z, c4[k].w};
            #pragma unroll
            for (int c = 0; c < NUM_C; c++) {
                float p = fminf(fmaxf(cv[c], 1e-4f), 1.0f - 1e-4f);
                bool is1 = (c == label);
                // t==1: w = 0.95*(1-p)^2, bce = -log(p)
                // t==0: w = 0.05*p^2,     bce = -log(1-p)
                float q = is1 ? (1.0f - p) : p;
                float w = (is1 ? 0.95f : 0.05f) * q * q;
                float bce = -__logf(1.0f - q);
                v0 = fmaf(w, bce, v0);
            }
        }

        if (positive) {
            float tx = bx  - ax[k];
            float ty = by  - ay[k];
            float ta = bal - aal[k];
            float dxr = fabsf(tx - rx[k]);
            float dyr = fabsf(ty - ry[k]);
            const float inv9 = 1.0f / 9.0f;
            float lx = (dxr <= inv9) ? (4.5f * dxr * dxr) : (dxr - 0.5f * inv9);
            float ly = (dyr <= inv9) ? (4.5f * dyr * dyr) : (dyr - 0.5f * inv9);
            v1 += lx + ly;
            v2 += fmaxf((fabsf(ta - ra[k]) - 10.0f) * 0.2f, 0.0f);
            v3 += 1.0f;
        }
    }

    // ---- block reduction: 4 quantities ----
    #pragma unroll
    for (int o = 16; o > 0; o >>= 1) {
        v0 += __shfl_down_sync(0xffffffffu, v0, o);
        v1 += __shfl_down_sync(0xffffffffu, v1, o);
        v2 += __shfl_down_sync(0xffffffffu, v2, o);
        v3 += __shfl_down_sync(0xffffffffu, v3, o);
    }
    __shared__ float red[BLOCK / 32][4];
    const int wid = tid >> 5, lid = tid & 31;
    if (lid == 0) {
        red[wid][0] = v0; red[wid][1] = v1; red[wid][2] = v2; red[wid][3] = v3;
    }
    __syncthreads();
    if (tid < 4) {
        float s = 0.0f;
        #pragma unroll
        for (int w = 0; w < BLOCK / 32; w++) s += red[w][tid];
        ((float*)&g_part[(size_t)b * GRIDX + blockIdx.x])[tid] = s;
        __threadfence();   // publish partials before the ticket increment
    }
    __syncthreads();

    // ---- last-block finalize (fused, no extra launches) ----
    __shared__ bool is_last;
    if (tid == 0) {
        unsigned v = atomicAdd(&g_count, 1u);
        is_last = (v == NBLOCKS - 1);
    }
    __syncthreads();
    if (!is_last) return;
    if (tid == 0) g_count = 0;   // reset for next graph replay

    // 8 warps, warp w reduces sample b=w over its 128 partials.
    __shared__ float s_res[NUM_B][3];
    const int w = tid >> 5, l = tid & 31;
    float4 acc = make_float4(0.f, 0.f, 0.f, 0.f);
    #pragma unroll
    for (int kk = 0; kk < GRIDX / 32; kk++) {
        float4 p = g_part[(size_t)w * GRIDX + l + 32 * kk];
        acc.x += p.x; acc.y += p.y; acc.z += p.z; acc.w += p.w;
    }
    #pragma unroll
    for (int o = 16; o > 0; o >>= 1) {
        acc.x += __shfl_down_sync(0xffffffffu, acc.x, o);
        acc.y += __shfl_down_sync(0xffffffffu, acc.y, o);
        acc.z += __shfl_down_sync(0xffffffffu, acc.z, o);
        acc.w += __shfl_down_sync(0xffffffffu, acc.w, o);
    }
    if (l == 0) {
        float denom = fmaxf(acc.w, 1.0f);
        s_res[w][0] = acc.x / denom;
        s_res[w][1] = acc.y / (2.0f * denom);
        s_res[w][2] = acc.z / denom;
    }
    __syncthreads();
    if (tid == 0) {
        float c = 0.f, x = 0.f, an = 0.f;
        #pragma unroll
        for (int bb = 0; bb < NUM_B; bb++) {
            c += s_res[bb][0]; x += s_res[bb][1]; an += s_res[bb][2];
        }
        out[0] = c  * (1.0f / NUM_B);
        out[1] = x  * (1.0f / NUM_B);
        out[2] = an * (1.0f / NUM_B);
    }
}

extern "C" void kernel_launch(void* const* d_in, const int* in_sizes, int n_in,
                              void* d_out, int out_size) {
    (void)in_sizes; (void)n_in; (void)out_size;
    const float* cls = (const float*)d_in[0];   // (B, A, C)
    const float* reg = (const float*)d_in[1];   // (B, A, 3)
    const float* anc = (const float*)d_in[2];   // (1, A, 3)
    const float* ann = (const float*)d_in[3];   // (B, M, 4)
    float* out = (float*)d_out;

    dim3 grid(GRIDX, NUM_B);
    focal_fused_kernel<<<grid, BLOCK>>>(cls, reg, anc, ann, out);
}